// round 11
// baseline (speedup 1.0000x reference)
#include <cuda_runtime.h>

// Problem constants (fixed by setup_inputs: H=480, W=1024, S=32, margin=10, step=4)
#define HH     480
#define WW     1024
#define SS     32
#define HWIMG  (HH*WW)          // 491520
#define NSLOT  61440            // 2*H*W/step^2
#define GXC    252
#define GYC    116
#define GG     (GXC*GYC)        // 29232
#define MARG   10
#define BB     240              // linker blocks (persistent, barrier participants)
#define MBLK   240              // mask-worker blocks
#define TT     256
#define NWARP  (TT/32)          // 8
#define WPI    (HWIMG/32)       // 15360 bitmask words per step
#define WPR    8                // occupancy words per grid row (256 bits >= GXC)
#define PWORDS 1024             // padded occupancy words (>= GYC*WPR = 928)
#define NSUB   8
#define SUBQ   (BB/NSUB)        // 30
#define PXB    2048             // pixels per mask block per step (240*2048 = HWIMG)

// Scratch (device globals; no allocations allowed)
__device__ __align__(16) unsigned g_bits[3][PWORDS];  // occupancy bitmask, 3-buffer rotation
__device__ __align__(128) unsigned g_on[(SS-1)*WPI];  // on-mask; produced in-flight, L2-only path
__device__ int g_slotCnt[2][NWARP][BB];               // parity-buffered (warp-row, block) free counts
__device__ unsigned g_onCnt[SS-1];                    // MONOTONIC per-slice completion counters
__device__ unsigned g_epoch;                          // MONOTONIC run counter
__device__ unsigned g_tgt;                            // this run's completion target (epoch*MBLK)
struct __align__(128) PadCnt { unsigned v; unsigned pad[31]; };
__device__ PadCnt g_barSub[NSUB];
__device__ PadCnt g_barMaster;
__device__ __align__(128) volatile unsigned g_barGen;

// empty pattern: pad bits (ix>=252 in-row, rows>=GYC) are permanently "occupied"
__device__ __forceinline__ unsigned epat(int w) {
    return (w >= GYC*WPR) ? 0xFFFFFFFFu : (((w & 7) == 7) ? 0xF0000000u : 0u);
}

__device__ __forceinline__ void gridbar() {
    __syncthreads();
    if (threadIdx.x == 0) {
        __threadfence();                       // release: publish this block's writes
        unsigned gen = g_barGen;               // read BEFORE arrival (else lost-release race)
        bool last = false;
        if (atomicAdd(&g_barSub[blockIdx.x & (NSUB - 1)].v, 1u) == SUBQ - 1u) {
            if (atomicAdd(&g_barMaster.v, 1u) == NSUB - 1u) last = true;
        }
        if (last) {
            g_barMaster.v = 0;
            #pragma unroll
            for (int i = 0; i < NSUB; i++) g_barSub[i].v = 0;
            __threadfence();
            g_barGen = gen + 1u;
        } else {
            while (g_barGen == gen) { }
        }
    }
    __syncthreads();
}

// ---- math helpers: byte-identical to R1..R9 (rel_err was 0.0) ----
__device__ __forceinline__ float bil4(float s00, float s01, float s10, float s11,
                                      float w00, float w01, float w10, float w11) {
    return fmaf(s11, w11, fmaf(s10, w10, fmaf(s00, w00, __fmul_rn(s01, w01))));
}

struct BilW {
    int ix0, ix1, iy0, iy1;
    float w00, w01, w10, w11;
};

__device__ __forceinline__ BilW mkw(float x, float y) {
    BilW b;
    float x0f = floorf(x), y0f = floorf(y);
    float wx1 = __fsub_rn(x, x0f); float wx0 = __fsub_rn(1.0f, wx1);
    float wy1 = __fsub_rn(y, y0f); float wy0 = __fsub_rn(1.0f, wy1);
    int ix0 = (int)x0f; ix0 = ix0 < 0 ? 0 : (ix0 > WW-1 ? WW-1 : ix0);
    int iy0 = (int)y0f; iy0 = iy0 < 0 ? 0 : (iy0 > HH-1 ? HH-1 : iy0);
    b.ix0 = ix0; b.ix1 = (ix0+1 > WW-1) ? WW-1 : ix0+1;
    b.iy0 = iy0; b.iy1 = (iy0+1 > HH-1) ? HH-1 : iy0+1;
    b.w00 = __fmul_rn(wy0, wx0); b.w01 = __fmul_rn(wy0, wx1);
    b.w10 = __fmul_rn(wy1, wx0); b.w11 = __fmul_rn(wy1, wx1);
    return b;
}

__device__ __forceinline__ float on_at(const float* __restrict__ fb0,
                                       const float* __restrict__ fb1,
                                       float a0, float a1, int py, int px) {
    float xt = __fadd_rn((float)px, a0);
    float yt = __fadd_rn((float)py, a1);
    BilW b = mkw(xt, yt);
    float f00 = fb0[b.iy0*WW+b.ix0], f01 = fb0[b.iy0*WW+b.ix1];
    float f10 = fb0[b.iy1*WW+b.ix0], f11 = fb0[b.iy1*WW+b.ix1];
    float g00 = fb1[b.iy0*WW+b.ix0], g01 = fb1[b.iy0*WW+b.ix1];
    float g10 = fb1[b.iy1*WW+b.ix0], g11 = fb1[b.iy1*WW+b.ix1];
    float f0 = bil4(f00, f01, f10, f11, b.w00, b.w01, b.w10, b.w11);
    float f1 = bil4(g00, g01, g10, g11, b.w00, b.w01, b.w10, b.w11);
    float d0 = __fadd_rn(a0, f0), d1 = __fadd_rn(a1, f1);
    float diff = __fsqrt_rn(fmaf(d1, d1, __fmul_rn(d0, d0)));
    float m1 = __fsqrt_rn(fmaf(a1, a1, __fmul_rn(a0, a0)));
    float m2 = __fsqrt_rn(fmaf(f1, f1, __fmul_rn(f0, f0)));
    float mag = __fmul_rn(0.5f, __fadd_rn(m1, m2));
    return (diff <= fmaf(0.01f, mag, 0.1f)) ? 1.0f : 0.0f;
}

// ---- mask-worker role: produce on-mask slices s = 0..SS-2 in ascending order ----
// ALL g_on stores are __stcg (L2, bypass L1) so data is at the coherence point
// strictly before the strong counter increment.
__device__ void mask_role(const float* __restrict__ ff, const float* __restrict__ fb,
                          int mb, int tid) {
    for (int s = 0; s < SS - 1; s++) {
        const float* ff0 = ff + (size_t)s * 2 * HWIMG;
        const float* ff1 = ff0 + HWIMG;
        const float* fb0 = fb + (size_t)s * 2 * HWIMG;
        const float* fb1 = fb0 + HWIMG;
        int base = mb * PXB;
        #pragma unroll
        for (int j = 0; j < PXB/TT; j++) {
            int p = base + j*TT + tid;               // coalesced per warp-iteration
            float a0 = ff0[p], a1 = ff1[p];
            float on = on_at(fb0, fb1, a0, a1, p >> 10, p & 1023);
            unsigned m = __ballot_sync(0xffffffffu, on != 0.0f);
            if ((tid & 31) == 0) __stcg(&g_on[s*WPI + (p >> 5)], m);
        }
        __threadfence();                             // order slice stores before signal
        __syncthreads();                             // all warps' fences done
        if (tid == 0) atomicAdd(&g_onCnt[s], 1u);    // strong, monotonic completion signal
    }
}

// ---------------- ONE fused kernel: 240 linker blocks + 240 mask blocks ----------------
// Linker identical to R9 except: on-probe loads are __ldcg (no L1 staleness channel),
// and each step first waits (strong RMW spin) for its on-mask slice.
__global__ void __launch_bounds__(TT, 4) k_fused(const float* __restrict__ ff,
                                                 const float* __restrict__ fb,
                                                 float* __restrict__ out) {
    const int tid = threadIdx.x;
    if (blockIdx.x >= BB) {                          // mask-worker role (exits when done)
        mask_role(ff, fb, blockIdx.x - BB, tid);
        return;
    }
    const int b    = blockIdx.x;
    const int lane = tid & 31;
    const int wid  = tid >> 5;
    const int t    = (b + BB*wid)*32 + lane;   // swizzled slot id

    float* X  = out;
    float* Y  = out + SS*NSLOT;
    float* St = out + 2*SS*NSLOT;

    __shared__ unsigned sh_bits[PWORDS];       // 4KB: full occupancy snapshot
    __shared__ int sh_pre[TT];                 // exclusive zero-count prefix per 4-word chunk
    __shared__ int sh_rowtot[NWARP], sh_wsum[NWARP], sh_woff[NWARP];
    __shared__ int sh_nf, sh_nc;

    // ---- init: per-thread persistent state + occupancy buffers + run target ----
    float myX, myY, mySt;
    {
        bool ing = t < GG;
        myX  = ing ? (float)(MARG + 4*(t % GXC)) : 0.0f;
        myY  = ing ? (float)(MARG + 4*(t / GXC)) : 0.0f;
        mySt = ing ? 0.0f : -1.0f;
        X[t] = myX; Y[t] = myY;            // row 0
    }
    if (b < 12) {                           // 12 blocks x 256 = 3072 = 3*PWORDS
        int w = ((b & 3) << 8) + tid;
        g_bits[b >> 2][w] = epat(w);
    }
    if (b == 0 && tid == 0)
        g_tgt = (atomicAdd(&g_epoch, 1u) + 1u) * (unsigned)MBLK;
    gridbar();   // occupancy init + target visible before step 0
    const unsigned tgt = __ldcg(&g_tgt);

    for (int s = 0; s < SS - 1; s++) {
        const int par = s & 1;
        unsigned* bm = g_bits[s % 3];                  // marked here, read in B'(s)
        unsigned* bc = g_bits[(s + 2) % 3];            // cleared here (marked at A(s+2))
        const float* ff0 = ff + (size_t)s * 2 * HWIMG;
        const float* ff1 = ff0 + HWIMG;
        const unsigned* onw = g_on + s*WPI;

        // wait for this step's on-mask slice: STRONG RMW spin (cannot be hoisted or stale)
        if (tid == 0) {
            while (atomicAdd(&g_onCnt[s], 0u) < tgt) { __nanosleep(200); }
        }
        __syncthreads();

        // ===== Phase A: clear future buffer, advance own slot, mark occupancy bits =====
        if (b < 4) { int w = (b << 8) + tid; bc[w] = epat(w); }

        bool freeflag = true;                 // == (updated Start < 0)
        float xw = 0.0f, yw = 0.0f;
        if (mySt >= 0.0f) {
            BilW bw = mkw(myX, myY);
            float u00 = ff0[bw.iy0*WW+bw.ix0], u01 = ff0[bw.iy0*WW+bw.ix1];
            float u10 = ff0[bw.iy1*WW+bw.ix0], u11 = ff0[bw.iy1*WW+bw.ix1];
            float v00 = ff1[bw.iy0*WW+bw.ix0], v01 = ff1[bw.iy0*WW+bw.ix1];
            float v10 = ff1[bw.iy1*WW+bw.ix0], v11 = ff1[bw.iy1*WW+bw.ix1];
            float uvx = bil4(u00, u01, u10, u11, bw.w00, bw.w01, bw.w10, bw.w11);
            float uvy = bil4(v00, v01, v10, v11, bw.w00, bw.w01, bw.w10, bw.w11);
            float xt = __fadd_rn(myX, uvx);
            float yt = __fadd_rn(myY, uvy);
            bool marg = (xt > (float)MARG) && (yt > (float)MARG) &&
                        (xt < (float)(WW - MARG)) && (yt < (float)(HH - MARG));
            if (marg) {
                // __ldcg probes: L2-coherent reads; reconstruct exactly 0.0f/1.0f
                float on00 = (float)((__ldcg(&onw[(bw.iy0<<5) + (bw.ix0>>5)]) >> (bw.ix0&31)) & 1u);
                float on01 = (float)((__ldcg(&onw[(bw.iy0<<5) + (bw.ix1>>5)]) >> (bw.ix1&31)) & 1u);
                float on10 = (float)((__ldcg(&onw[(bw.iy1<<5) + (bw.ix0>>5)]) >> (bw.ix0&31)) & 1u);
                float on11 = (float)((__ldcg(&onw[(bw.iy1<<5) + (bw.ix1>>5)]) >> (bw.ix1&31)) & 1u);
                float onv = bil4(on00, on01, on10, on11, bw.w00, bw.w01, bw.w10, bw.w11);
                if (onv > 0.5f) {
                    freeflag = false;
                    xw = xt; yw = yt;
                    int oy = (int)yt, ox = (int)xt;
                    int iylo = (oy - 9) / 4; if (iylo < 0) iylo = 0;
                    int iyhi = (oy - 8) / 4; if (iyhi > GYC-1) iyhi = GYC-1;
                    int ixlo = (ox - 9) / 4; if (ixlo < 0) ixlo = 0;
                    int ixhi = (ox - 8) / 4; if (ixhi > GXC-1) ixhi = GXC-1;
                    for (int iy = iylo; iy <= iyhi; iy++) {
                        int w = (iy << 3) + (ixlo >> 5);
                        unsigned m1 = 1u << (ixlo & 31);
                        if (ixhi > ixlo) {
                            if ((ixlo & 31) == 31) {
                                atomicOr(&bm[w], m1);
                                atomicOr(&bm[w + 1], 1u);
                            } else {
                                atomicOr(&bm[w], m1 | (m1 << 1));
                            }
                        } else {
                            atomicOr(&bm[w], m1);
                        }
                    }
                }
            }
        }
        if (freeflag) mySt = -1.0f;
        myX = xw; myY = yw;
        X[(s+1)*NSLOT + t] = xw;
        Y[(s+1)*NSLOT + t] = yw;

        unsigned amask = __ballot_sync(0xffffffffu, freeflag);
        if (lane == 0) g_slotCnt[par][wid][b] = __popc(amask);

        gridbar();   // occupancy marks + slot counts + row s+1 visible

        // ===== Phase B': full-map snapshot + local scan + slot ranking + self-birth =====
        uint4 v = __ldcg((const uint4*)bm + tid);
        sh_bits[tid*4 + 0] = v.x; sh_bits[tid*4 + 1] = v.y;
        sh_bits[tid*4 + 2] = v.z; sh_bits[tid*4 + 3] = v.w;
        int zc = 128 - (__popc(v.x) + __popc(v.y) + __popc(v.z) + __popc(v.w));

        int inc = zc;
        #pragma unroll
        for (int d = 1; d < 32; d <<= 1) {
            int n = __shfl_up_sync(0xffffffffu, inc, d);
            if (lane >= d) inc += n;
        }
        if (lane == 31) sh_wsum[wid] = inc;

        int rcnt = 0, rpre = 0;
        #pragma unroll
        for (int k = 0; k < 8; k++) {
            int i = lane + 32*k;
            if (i < BB) {
                int c = __ldcg(&g_slotCnt[par][wid][i]);
                rcnt += c;
                if (i < b) rpre += c;
            }
        }
        int rowtot = __reduce_add_sync(0xffffffffu, rcnt);
        int rowpre = __reduce_add_sync(0xffffffffu, rpre);
        if (lane == 0) sh_rowtot[wid] = rowtot;
        __syncthreads();
        if (tid == 0) {
            int run = 0;
            #pragma unroll
            for (int i = 0; i < NWARP; i++) { int c = sh_wsum[i]; sh_woff[i] = run; run += c; }
            sh_nc = run;
            int nfr = 0;
            #pragma unroll
            for (int i = 0; i < NWARP; i++) nfr += sh_rowtot[i];
            sh_nf = nfr;
        }
        __syncthreads();
        sh_pre[tid] = sh_woff[wid] + inc - zc;
        int base = rowpre;
        #pragma unroll
        for (int i = 0; i < NWARP; i++) if (i < wid) base += sh_rowtot[i];
        int myrank = freeflag ? base + __popc(amask & ((1u << lane) - 1u)) : -1;
        __syncthreads();

        int m = sh_nf < sh_nc ? sh_nf : sh_nc;
        if (myrank >= 0 && myrank < m) {
            int r = myrank;
            int lo = 0, hi = TT - 1;
            while (lo < hi) {
                int mid = (lo + hi + 1) >> 1;
                if (sh_pre[mid] <= r) lo = mid; else hi = mid - 1;
            }
            int k = r - sh_pre[lo];
            int wsel = -1, bit = 0;
            #pragma unroll
            for (int j = 0; j < 4; j++) {
                unsigned zw = ~sh_bits[lo*4 + j];
                int nz = __popc(zw);
                if (wsel < 0) {
                    if (k < nz) { wsel = lo*4 + j; bit = __fns(zw, 0, k + 1); }
                    else k -= nz;
                }
            }
            int iy = wsel >> 3;
            int ix = ((wsel & 7) << 5) | bit;
            myX = (float)(MARG + 4*ix);
            myY = (float)(MARG + 4*iy);
            mySt = (float)(s + 1);
            X[(s+1)*NSLOT + t] = myX;
            Y[(s+1)*NSLOT + t] = myY;
        }
    }

    St[t] = mySt;
}

extern "C" void kernel_launch(void* const* d_in, const int* in_sizes, int n_in,
                              void* d_out, int out_size) {
    (void)in_sizes; (void)n_in; (void)out_size;
    const float* ff = (const float*)d_in[0];
    const float* fb = (const float*)d_in[1];
    float* out = (float*)d_out;
    k_fused<<<BB + MBLK, TT>>>(ff, fb, out);
}

// round 12
// speedup vs baseline: 1.1311x; 1.1311x over previous
#include <cuda_runtime.h>

// Problem constants (fixed by setup_inputs: H=480, W=1024, S=32, margin=10, step=4)
#define HH     480
#define WW     1024
#define SS     32
#define HWIMG  (HH*WW)          // 491520
#define NSLOT  61440            // 2*H*W/step^2
#define GXC    252
#define GYC    116
#define GG     (GXC*GYC)        // 29232
#define MARG   10
#define BB     240              // linker blocks (persistent, barrier participants)
#define TT     256
#define NWARP  (TT/32)          // 8
#define WPI    (HWIMG/32)       // 15360 bitmask words per step
#define WPR    8                // occupancy words per grid row (256 bits >= GXC)
#define PWORDS 1024             // padded occupancy words (>= GYC*WPR = 928)
#define NSUB   8
#define SUBQ   (BB/NSUB)        // 30
#define LPS    960              // one-shot mask-lets per slice (HWIMG / 512)
#define NLETS  ((SS-1)*LPS)     // 29760

// Scratch (device globals; no allocations allowed)
__device__ __align__(16) unsigned g_bits[3][PWORDS];  // occupancy bitmask, 3-buffer rotation
__device__ __align__(128) unsigned g_on[(SS-1)*WPI];  // on-mask; produced in-flight, L2-only path
__device__ int g_slotCnt[2][NWARP][BB];               // parity-buffered (warp-row, block) free counts
__device__ unsigned g_onCnt[SS-1];                    // MONOTONIC per-slice completion counters
__device__ unsigned g_epoch;                          // MONOTONIC run counter
__device__ unsigned g_tgt;                            // this run's completion target (epoch*LPS)
struct __align__(128) PadCnt { unsigned v; unsigned pad[31]; };
__device__ PadCnt g_barSub[NSUB];
__device__ PadCnt g_barMaster;
__device__ __align__(128) volatile unsigned g_barGen;

// empty pattern: pad bits (ix>=252 in-row, rows>=GYC) are permanently "occupied"
__device__ __forceinline__ unsigned epat(int w) {
    return (w >= GYC*WPR) ? 0xFFFFFFFFu : (((w & 7) == 7) ? 0xF0000000u : 0u);
}

__device__ __forceinline__ void gridbar() {
    __syncthreads();
    if (threadIdx.x == 0) {
        __threadfence();                       // release: publish this block's writes
        unsigned gen = g_barGen;               // read BEFORE arrival (else lost-release race)
        bool last = false;
        if (atomicAdd(&g_barSub[blockIdx.x & (NSUB - 1)].v, 1u) == SUBQ - 1u) {
            if (atomicAdd(&g_barMaster.v, 1u) == NSUB - 1u) last = true;
        }
        if (last) {
            g_barMaster.v = 0;
            #pragma unroll
            for (int i = 0; i < NSUB; i++) g_barSub[i].v = 0;
            __threadfence();
            g_barGen = gen + 1u;
        } else {
            while (g_barGen == gen) { }
        }
    }
    __syncthreads();
}

// ---- math helpers: byte-identical to R1..R11 (rel_err was 0.0) ----
__device__ __forceinline__ float bil4(float s00, float s01, float s10, float s11,
                                      float w00, float w01, float w10, float w11) {
    return fmaf(s11, w11, fmaf(s10, w10, fmaf(s00, w00, __fmul_rn(s01, w01))));
}

struct BilW {
    int ix0, ix1, iy0, iy1;
    float w00, w01, w10, w11;
};

__device__ __forceinline__ BilW mkw(float x, float y) {
    BilW b;
    float x0f = floorf(x), y0f = floorf(y);
    float wx1 = __fsub_rn(x, x0f); float wx0 = __fsub_rn(1.0f, wx1);
    float wy1 = __fsub_rn(y, y0f); float wy0 = __fsub_rn(1.0f, wy1);
    int ix0 = (int)x0f; ix0 = ix0 < 0 ? 0 : (ix0 > WW-1 ? WW-1 : ix0);
    int iy0 = (int)y0f; iy0 = iy0 < 0 ? 0 : (iy0 > HH-1 ? HH-1 : iy0);
    b.ix0 = ix0; b.ix1 = (ix0+1 > WW-1) ? WW-1 : ix0+1;
    b.iy0 = iy0; b.iy1 = (iy0+1 > HH-1) ? HH-1 : iy0+1;
    b.w00 = __fmul_rn(wy0, wx0); b.w01 = __fmul_rn(wy0, wx1);
    b.w10 = __fmul_rn(wy1, wx0); b.w11 = __fmul_rn(wy1, wx1);
    return b;
}

__device__ __forceinline__ float on_at(const float* __restrict__ fb0,
                                       const float* __restrict__ fb1,
                                       float a0, float a1, int py, int px) {
    float xt = __fadd_rn((float)px, a0);
    float yt = __fadd_rn((float)py, a1);
    BilW b = mkw(xt, yt);
    float f00 = fb0[b.iy0*WW+b.ix0], f01 = fb0[b.iy0*WW+b.ix1];
    float f10 = fb0[b.iy1*WW+b.ix0], f11 = fb0[b.iy1*WW+b.ix1];
    float g00 = fb1[b.iy0*WW+b.ix0], g01 = fb1[b.iy0*WW+b.ix1];
    float g10 = fb1[b.iy1*WW+b.ix0], g11 = fb1[b.iy1*WW+b.ix1];
    float f0 = bil4(f00, f01, f10, f11, b.w00, b.w01, b.w10, b.w11);
    float f1 = bil4(g00, g01, g10, g11, b.w00, b.w01, b.w10, b.w11);
    float d0 = __fadd_rn(a0, f0), d1 = __fadd_rn(a1, f1);
    float diff = __fsqrt_rn(fmaf(d1, d1, __fmul_rn(d0, d0)));
    float m1 = __fsqrt_rn(fmaf(a1, a1, __fmul_rn(a0, a0)));
    float m2 = __fsqrt_rn(fmaf(f1, f1, __fmul_rn(f0, f0)));
    float mag = __fmul_rn(0.5f, __fadd_rn(m1, m2));
    return (diff <= fmaf(0.01f, mag, 0.1f)) ? 1.0f : 0.0f;
}

// ---- one-shot mask-let: 512 px of one slice, then EXIT (slots churn -> latency hiding) ----
// Producer recipe identical to R11 (passed): __stcg data -> threadfence -> syncthreads -> atomicAdd.
__device__ void mask_let(const float* __restrict__ ff, const float* __restrict__ fb,
                         int mb, int tid) {
    int s = mb / LPS;
    int base = (mb - s * LPS) * 512;
    const float* ff0 = ff + (size_t)s * 2 * HWIMG;
    const float* ff1 = ff0 + HWIMG;
    const float* fb0 = fb + (size_t)s * 2 * HWIMG;
    const float* fb1 = fb0 + HWIMG;
    int p = base + tid;                              // first pixel
    int q = p + TT;                                  // second pixel (independent word)
    float a0 = ff0[p], a1 = ff1[p];
    float b0 = ff0[q], b1 = ff1[q];
    float on1 = on_at(fb0, fb1, a0, a1, p >> 10, p & 1023);
    float on2 = on_at(fb0, fb1, b0, b1, q >> 10, q & 1023);
    unsigned m1 = __ballot_sync(0xffffffffu, on1 != 0.0f);
    unsigned m2 = __ballot_sync(0xffffffffu, on2 != 0.0f);
    if ((tid & 31) == 0) {
        __stcg(&g_on[s*WPI + (p >> 5)], m1);
        __stcg(&g_on[s*WPI + (q >> 5)], m2);
    }
    __threadfence();                                 // order slice stores before signal
    __syncthreads();                                 // all warps' fences done
    if (tid == 0) atomicAdd(&g_onCnt[s], 1u);        // strong, monotonic completion signal
}

// ---------------- ONE fused kernel: 240 linker blocks + 29760 one-shot mask-lets ----------------
// Linker identical to R11 (passed): strong-RMW slice wait, __ldcg on-probes, one gridbar per step.
__global__ void __launch_bounds__(TT, 4) k_fused(const float* __restrict__ ff,
                                                 const float* __restrict__ fb,
                                                 float* __restrict__ out) {
    const int tid = threadIdx.x;
    if (blockIdx.x >= BB) {                          // mask-let role (exits immediately)
        mask_let(ff, fb, blockIdx.x - BB, tid);
        return;
    }
    const int b    = blockIdx.x;
    const int lane = tid & 31;
    const int wid  = tid >> 5;
    const int t    = (b + BB*wid)*32 + lane;   // swizzled slot id

    float* X  = out;
    float* Y  = out + SS*NSLOT;
    float* St = out + 2*SS*NSLOT;

    __shared__ unsigned sh_bits[PWORDS];       // 4KB: full occupancy snapshot
    __shared__ int sh_pre[TT];                 // exclusive zero-count prefix per 4-word chunk
    __shared__ int sh_rowtot[NWARP], sh_wsum[NWARP], sh_woff[NWARP];
    __shared__ int sh_nf, sh_nc;

    // ---- init: per-thread persistent state + occupancy buffers + run target ----
    float myX, myY, mySt;
    {
        bool ing = t < GG;
        myX  = ing ? (float)(MARG + 4*(t % GXC)) : 0.0f;
        myY  = ing ? (float)(MARG + 4*(t / GXC)) : 0.0f;
        mySt = ing ? 0.0f : -1.0f;
        X[t] = myX; Y[t] = myY;            // row 0
    }
    if (b < 12) {                           // 12 blocks x 256 = 3072 = 3*PWORDS
        int w = ((b & 3) << 8) + tid;
        g_bits[b >> 2][w] = epat(w);
    }
    if (b == 0 && tid == 0)
        g_tgt = (atomicAdd(&g_epoch, 1u) + 1u) * (unsigned)LPS;
    gridbar();   // occupancy init + target visible before step 0
    const unsigned tgt = __ldcg(&g_tgt);

    for (int s = 0; s < SS - 1; s++) {
        const int par = s & 1;
        unsigned* bm = g_bits[s % 3];                  // marked here, read in B'(s)
        unsigned* bc = g_bits[(s + 2) % 3];            // cleared here (marked at A(s+2))
        const float* ff0 = ff + (size_t)s * 2 * HWIMG;
        const float* ff1 = ff0 + HWIMG;
        const unsigned* onw = g_on + s*WPI;

        // wait for this step's on-mask slice: STRONG RMW spin (cannot be hoisted or stale)
        if (tid == 0) {
            while (atomicAdd(&g_onCnt[s], 0u) < tgt) { __nanosleep(200); }
        }
        __syncthreads();

        // ===== Phase A: clear future buffer, advance own slot, mark occupancy bits =====
        if (b < 4) { int w = (b << 8) + tid; bc[w] = epat(w); }

        bool freeflag = true;                 // == (updated Start < 0)
        float xw = 0.0f, yw = 0.0f;
        if (mySt >= 0.0f) {
            BilW bw = mkw(myX, myY);
            float u00 = ff0[bw.iy0*WW+bw.ix0], u01 = ff0[bw.iy0*WW+bw.ix1];
            float u10 = ff0[bw.iy1*WW+bw.ix0], u11 = ff0[bw.iy1*WW+bw.ix1];
            float v00 = ff1[bw.iy0*WW+bw.ix0], v01 = ff1[bw.iy0*WW+bw.ix1];
            float v10 = ff1[bw.iy1*WW+bw.ix0], v11 = ff1[bw.iy1*WW+bw.ix1];
            float uvx = bil4(u00, u01, u10, u11, bw.w00, bw.w01, bw.w10, bw.w11);
            float uvy = bil4(v00, v01, v10, v11, bw.w00, bw.w01, bw.w10, bw.w11);
            float xt = __fadd_rn(myX, uvx);
            float yt = __fadd_rn(myY, uvy);
            bool marg = (xt > (float)MARG) && (yt > (float)MARG) &&
                        (xt < (float)(WW - MARG)) && (yt < (float)(HH - MARG));
            if (marg) {
                // __ldcg probes: L2-coherent reads; reconstruct exactly 0.0f/1.0f
                float on00 = (float)((__ldcg(&onw[(bw.iy0<<5) + (bw.ix0>>5)]) >> (bw.ix0&31)) & 1u);
                float on01 = (float)((__ldcg(&onw[(bw.iy0<<5) + (bw.ix1>>5)]) >> (bw.ix1&31)) & 1u);
                float on10 = (float)((__ldcg(&onw[(bw.iy1<<5) + (bw.ix0>>5)]) >> (bw.ix0&31)) & 1u);
                float on11 = (float)((__ldcg(&onw[(bw.iy1<<5) + (bw.ix1>>5)]) >> (bw.ix1&31)) & 1u);
                float onv = bil4(on00, on01, on10, on11, bw.w00, bw.w01, bw.w10, bw.w11);
                if (onv > 0.5f) {
                    freeflag = false;
                    xw = xt; yw = yt;
                    int oy = (int)yt, ox = (int)xt;
                    int iylo = (oy - 9) / 4; if (iylo < 0) iylo = 0;
                    int iyhi = (oy - 8) / 4; if (iyhi > GYC-1) iyhi = GYC-1;
                    int ixlo = (ox - 9) / 4; if (ixlo < 0) ixlo = 0;
                    int ixhi = (ox - 8) / 4; if (ixhi > GXC-1) ixhi = GXC-1;
                    for (int iy = iylo; iy <= iyhi; iy++) {
                        int w = (iy << 3) + (ixlo >> 5);
                        unsigned m1 = 1u << (ixlo & 31);
                        if (ixhi > ixlo) {
                            if ((ixlo & 31) == 31) {
                                atomicOr(&bm[w], m1);
                                atomicOr(&bm[w + 1], 1u);
                            } else {
                                atomicOr(&bm[w], m1 | (m1 << 1));
                            }
                        } else {
                            atomicOr(&bm[w], m1);
                        }
                    }
                }
            }
        }
        if (freeflag) mySt = -1.0f;
        myX = xw; myY = yw;
        X[(s+1)*NSLOT + t] = xw;
        Y[(s+1)*NSLOT + t] = yw;

        unsigned amask = __ballot_sync(0xffffffffu, freeflag);
        if (lane == 0) g_slotCnt[par][wid][b] = __popc(amask);

        gridbar();   // occupancy marks + slot counts + row s+1 visible

        // ===== Phase B': full-map snapshot + local scan + slot ranking + self-birth =====
        uint4 v = __ldcg((const uint4*)bm + tid);
        sh_bits[tid*4 + 0] = v.x; sh_bits[tid*4 + 1] = v.y;
        sh_bits[tid*4 + 2] = v.z; sh_bits[tid*4 + 3] = v.w;
        int zc = 128 - (__popc(v.x) + __popc(v.y) + __popc(v.z) + __popc(v.w));

        int inc = zc;
        #pragma unroll
        for (int d = 1; d < 32; d <<= 1) {
            int n = __shfl_up_sync(0xffffffffu, inc, d);
            if (lane >= d) inc += n;
        }
        if (lane == 31) sh_wsum[wid] = inc;

        int rcnt = 0, rpre = 0;
        #pragma unroll
        for (int k = 0; k < 8; k++) {
            int i = lane + 32*k;
            if (i < BB) {
                int c = __ldcg(&g_slotCnt[par][wid][i]);
                rcnt += c;
                if (i < b) rpre += c;
            }
        }
        int rowtot = __reduce_add_sync(0xffffffffu, rcnt);
        int rowpre = __reduce_add_sync(0xffffffffu, rpre);
        if (lane == 0) sh_rowtot[wid] = rowtot;
        __syncthreads();
        if (tid == 0) {
            int run = 0;
            #pragma unroll
            for (int i = 0; i < NWARP; i++) { int c = sh_wsum[i]; sh_woff[i] = run; run += c; }
            sh_nc = run;
            int nfr = 0;
            #pragma unroll
            for (int i = 0; i < NWARP; i++) nfr += sh_rowtot[i];
            sh_nf = nfr;
        }
        __syncthreads();
        sh_pre[tid] = sh_woff[wid] + inc - zc;
        int base = rowpre;
        #pragma unroll
        for (int i = 0; i < NWARP; i++) if (i < wid) base += sh_rowtot[i];
        int myrank = freeflag ? base + __popc(amask & ((1u << lane) - 1u)) : -1;
        __syncthreads();

        int m = sh_nf < sh_nc ? sh_nf : sh_nc;
        if (myrank >= 0 && myrank < m) {
            int r = myrank;
            int lo = 0, hi = TT - 1;
            while (lo < hi) {
                int mid = (lo + hi + 1) >> 1;
                if (sh_pre[mid] <= r) lo = mid; else hi = mid - 1;
            }
            int k = r - sh_pre[lo];
            int wsel = -1, bit = 0;
            #pragma unroll
            for (int j = 0; j < 4; j++) {
                unsigned zw = ~sh_bits[lo*4 + j];
                int nz = __popc(zw);
                if (wsel < 0) {
                    if (k < nz) { wsel = lo*4 + j; bit = __fns(zw, 0, k + 1); }
                    else k -= nz;
                }
            }
            int iy = wsel >> 3;
            int ix = ((wsel & 7) << 5) | bit;
            myX = (float)(MARG + 4*ix);
            myY = (float)(MARG + 4*iy);
            mySt = (float)(s + 1);
            X[(s+1)*NSLOT + t] = myX;
            Y[(s+1)*NSLOT + t] = myY;
        }
    }

    St[t] = mySt;
}

extern "C" void kernel_launch(void* const* d_in, const int* in_sizes, int n_in,
                              void* d_out, int out_size) {
    (void)in_sizes; (void)n_in; (void)out_size;
    const float* ff = (const float*)d_in[0];
    const float* fb = (const float*)d_in[1];
    float* out = (float*)d_out;
    k_fused<<<BB + NLETS, TT>>>(ff, fb, out);
}

// round 13
// speedup vs baseline: 1.1892x; 1.0514x over previous
#include <cuda_runtime.h>

// Problem constants (fixed by setup_inputs: H=480, W=1024, S=32, margin=10, step=4)
#define HH     480
#define WW     1024
#define SS     32
#define HWIMG  (HH*WW)          // 491520
#define NSLOT  61440            // 2*H*W/step^2
#define GXC    252
#define GYC    116
#define GG     (GXC*GYC)        // 29232
#define MARG   10
#define BB     240              // persistent linker grid: 240 blocks x 256 = NSLOT threads
#define TT     256
#define NWARP  (TT/32)          // 8
#define WPI    (HWIMG/32)       // 15360 bitmask words per step
#define WPR    8                // occupancy words per grid row (256 bits >= GXC)
#define PWORDS 1024             // padded occupancy words (>= GYC*WPR = 928)
#define NSUB   8
#define SUBQ   (BB/NSUB)        // 30
#define QTR    (HWIMG/4)        // 122880 (divisible by 32)

// Scratch (device globals; no allocations allowed)
// Occupancy bitmask, 3-buffer rotation (race-free): A(s) marks buf(s%3) and clears
// buf((s+1)%3); B'(s) reads buf(s%3). Every mark/read/clear pair is separated by a
// gridbar: buf(x) cleared at A(x-1), marked at A(x), read at B'(x), next cleared at
// A(x+2) — barriers at the end of each A between all of them.
__device__ __align__(16) unsigned g_bits[3][PWORDS];
__device__ __align__(128) unsigned g_on[(SS-1)*WPI];  // precomputed fwd-bwd consistency bitmask
__device__ int g_slotCnt[2][NWARP][BB];               // parity-buffered (warp-row, block) free counts
struct __align__(128) PadCnt { unsigned v; unsigned pad[31]; };
__device__ PadCnt g_barSub[NSUB];
__device__ PadCnt g_barMaster;
__device__ __align__(128) volatile unsigned g_barGen;

// empty pattern: pad bits (ix>=252 in-row, rows>=GYC) are permanently "occupied"
__device__ __forceinline__ unsigned epat(int w) {
    return (w >= GYC*WPR) ? 0xFFFFFFFFu : (((w & 7) == 7) ? 0xF0000000u : 0u);
}

__device__ __forceinline__ void gridbar() {
    __syncthreads();
    if (threadIdx.x == 0) {
        __threadfence();                       // release: publish this block's writes
        unsigned gen = g_barGen;               // read BEFORE arrival (else lost-release race)
        bool last = false;
        if (atomicAdd(&g_barSub[blockIdx.x & (NSUB - 1)].v, 1u) == SUBQ - 1u) {
            if (atomicAdd(&g_barMaster.v, 1u) == NSUB - 1u) last = true;
        }
        if (last) {
            g_barMaster.v = 0;
            #pragma unroll
            for (int i = 0; i < NSUB; i++) g_barSub[i].v = 0;
            __threadfence();
            g_barGen = gen + 1u;
        } else {
            while (g_barGen == gen) { }
        }
    }
    __syncthreads();
}

// ---- math helpers: byte-identical to R1..R12 (rel_err was 0.0) ----
__device__ __forceinline__ float bil4(float s00, float s01, float s10, float s11,
                                      float w00, float w01, float w10, float w11) {
    return fmaf(s11, w11, fmaf(s10, w10, fmaf(s00, w00, __fmul_rn(s01, w01))));
}

struct BilW {
    int ix0, ix1, iy0, iy1;
    float w00, w01, w10, w11;
};

__device__ __forceinline__ BilW mkw(float x, float y) {
    BilW b;
    float x0f = floorf(x), y0f = floorf(y);
    float wx1 = __fsub_rn(x, x0f); float wx0 = __fsub_rn(1.0f, wx1);
    float wy1 = __fsub_rn(y, y0f); float wy0 = __fsub_rn(1.0f, wy1);
    int ix0 = (int)x0f; ix0 = ix0 < 0 ? 0 : (ix0 > WW-1 ? WW-1 : ix0);
    int iy0 = (int)y0f; iy0 = iy0 < 0 ? 0 : (iy0 > HH-1 ? HH-1 : iy0);
    b.ix0 = ix0; b.ix1 = (ix0+1 > WW-1) ? WW-1 : ix0+1;
    b.iy0 = iy0; b.iy1 = (iy0+1 > HH-1) ? HH-1 : iy0+1;
    b.w00 = __fmul_rn(wy0, wx0); b.w01 = __fmul_rn(wy0, wx1);
    b.w10 = __fmul_rn(wy1, wx0); b.w11 = __fmul_rn(wy1, wx1);
    return b;
}

__device__ __forceinline__ float on_at(const float* __restrict__ fb0,
                                       const float* __restrict__ fb1,
                                       float a0, float a1, int py, int px) {
    float xt = __fadd_rn((float)px, a0);
    float yt = __fadd_rn((float)py, a1);
    BilW b = mkw(xt, yt);
    float f00 = fb0[b.iy0*WW+b.ix0], f01 = fb0[b.iy0*WW+b.ix1];
    float f10 = fb0[b.iy1*WW+b.ix0], f11 = fb0[b.iy1*WW+b.ix1];
    float g00 = fb1[b.iy0*WW+b.ix0], g01 = fb1[b.iy0*WW+b.ix1];
    float g10 = fb1[b.iy1*WW+b.ix0], g11 = fb1[b.iy1*WW+b.ix1];
    float f0 = bil4(f00, f01, f10, f11, b.w00, b.w01, b.w10, b.w11);
    float f1 = bil4(g00, g01, g10, g11, b.w00, b.w01, b.w10, b.w11);
    float d0 = __fadd_rn(a0, f0), d1 = __fadd_rn(a1, f1);
    float diff = __fsqrt_rn(fmaf(d1, d1, __fmul_rn(d0, d0)));
    float m1 = __fsqrt_rn(fmaf(a1, a1, __fmul_rn(a0, a0)));
    float m2 = __fsqrt_rn(fmaf(f1, f1, __fmul_rn(f0, f0)));
    float mag = __fmul_rn(0.5f, __fadd_rn(m1, m2));
    return (diff <= fmaf(0.01f, mag, 0.1f)) ? 1.0f : 0.0f;
}

// ---------------- precompute: 4 px/thread, scalar loads, 4 independent eval chains ----------------
__global__ void __launch_bounds__(256) k_onmask(const float* __restrict__ ff,
                                                const float* __restrict__ fb) {
    int s = blockIdx.y;
    int p0 = blockIdx.x * 256 + threadIdx.x;
    int p1 = p0 + QTR;
    int p2 = p0 + 2*QTR;
    int p3 = p0 + 3*QTR;
    const float* ff0 = ff + (size_t)s * 2 * HWIMG;
    const float* ff1 = ff0 + HWIMG;
    const float* fb0 = fb + (size_t)s * 2 * HWIMG;
    const float* fb1 = fb0 + HWIMG;
    float a0 = ff0[p0], a1 = ff1[p0];
    float b0 = ff0[p1], b1 = ff1[p1];
    float c0 = ff0[p2], c1 = ff1[p2];
    float d0 = ff0[p3], d1 = ff1[p3];
    float o0 = on_at(fb0, fb1, a0, a1, p0 >> 10, p0 & 1023);
    float o1 = on_at(fb0, fb1, b0, b1, p1 >> 10, p1 & 1023);
    float o2 = on_at(fb0, fb1, c0, c1, p2 >> 10, p2 & 1023);
    float o3 = on_at(fb0, fb1, d0, d1, p3 >> 10, p3 & 1023);
    unsigned m0 = __ballot_sync(0xffffffffu, o0 != 0.0f);
    unsigned m1 = __ballot_sync(0xffffffffu, o1 != 0.0f);
    unsigned m2 = __ballot_sync(0xffffffffu, o2 != 0.0f);
    unsigned m3 = __ballot_sync(0xffffffffu, o3 != 0.0f);
    if ((threadIdx.x & 31) == 0) {
        g_on[s*WPI + (p0 >> 5)] = m0;
        g_on[s*WPI + (p1 >> 5)] = m1;
        g_on[s*WPI + (p2 >> 5)] = m2;
        g_on[s*WPI + (p3 >> 5)] = m3;
    }
}

// ---------------- persistent serial kernel, ONE grid barrier per step (R9 + race fix) ----------------
// Slot ownership warp-swizzled: thread (b, warp wi, lane) owns slot t = (b + BB*wi)*32 + lane.
__global__ void __launch_bounds__(TT, 2) k_linker(const float* __restrict__ ff,
                                                  float* __restrict__ out) {
    const int tid  = threadIdx.x;
    const int b    = blockIdx.x;
    const int lane = tid & 31;
    const int wid  = tid >> 5;
    const int t    = (b + BB*wid)*32 + lane;   // swizzled slot id

    float* X  = out;
    float* Y  = out + SS*NSLOT;
    float* St = out + 2*SS*NSLOT;

    __shared__ unsigned sh_bits[PWORDS];       // 4KB: full occupancy snapshot
    __shared__ int sh_pre[TT];                 // exclusive zero-count prefix per 4-word chunk
    __shared__ int sh_rowtot[NWARP], sh_wsum[NWARP], sh_woff[NWARP];
    __shared__ int sh_nf, sh_nc;

    // ---- init: per-thread persistent state + all 3 occupancy buffers to empty pattern ----
    float myX, myY, mySt;
    {
        bool ing = t < GG;
        myX  = ing ? (float)(MARG + 4*(t % GXC)) : 0.0f;
        myY  = ing ? (float)(MARG + 4*(t / GXC)) : 0.0f;
        mySt = ing ? 0.0f : -1.0f;
        X[t] = myX; Y[t] = myY;            // row 0
    }
    if (b < 12) {                           // 12 blocks x 256 = 3072 = 3*PWORDS
        int w = ((b & 3) << 8) + tid;
        g_bits[b >> 2][w] = epat(w);
    }
    gridbar();   // occupancy init visible before A(0) marks

    for (int s = 0; s < SS - 1; s++) {
        const int par = s & 1;
        unsigned* bm = g_bits[s % 3];                  // marked here, read in B'(s)
        unsigned* bc = g_bits[(s + 1) % 3];            // cleared here (marked at A(s+1)) — race-free
        const float* ff0 = ff + (size_t)s * 2 * HWIMG;
        const float* ff1 = ff0 + HWIMG;
        const unsigned* onw = g_on + s*WPI;

        // ===== Phase A: clear next buffer, advance own slot, mark occupancy bits =====
        if (b < 4) { int w = (b << 8) + tid; bc[w] = epat(w); }

        bool freeflag = true;                 // == (updated Start < 0)
        float xw = 0.0f, yw = 0.0f;
        if (mySt >= 0.0f) {
            BilW bw = mkw(myX, myY);
            float u00 = ff0[bw.iy0*WW+bw.ix0], u01 = ff0[bw.iy0*WW+bw.ix1];
            float u10 = ff0[bw.iy1*WW+bw.ix0], u11 = ff0[bw.iy1*WW+bw.ix1];
            float v00 = ff1[bw.iy0*WW+bw.ix0], v01 = ff1[bw.iy0*WW+bw.ix1];
            float v10 = ff1[bw.iy1*WW+bw.ix0], v11 = ff1[bw.iy1*WW+bw.ix1];
            float uvx = bil4(u00, u01, u10, u11, bw.w00, bw.w01, bw.w10, bw.w11);
            float uvy = bil4(v00, v01, v10, v11, bw.w00, bw.w01, bw.w10, bw.w11);
            float xt = __fadd_rn(myX, uvx);
            float yt = __fadd_rn(myY, uvy);
            bool marg = (xt > (float)MARG) && (yt > (float)MARG) &&
                        (xt < (float)(WW - MARG)) && (yt < (float)(HH - MARG));
            if (marg) {
                // bitmask probes reconstruct exactly 0.0f/1.0f (bit-identical to on_at)
                float on00 = (float)((onw[(bw.iy0<<5) + (bw.ix0>>5)] >> (bw.ix0&31)) & 1u);
                float on01 = (float)((onw[(bw.iy0<<5) + (bw.ix1>>5)] >> (bw.ix1&31)) & 1u);
                float on10 = (float)((onw[(bw.iy1<<5) + (bw.ix0>>5)] >> (bw.ix0&31)) & 1u);
                float on11 = (float)((onw[(bw.iy1<<5) + (bw.ix1>>5)] >> (bw.ix1&31)) & 1u);
                float onv = bil4(on00, on01, on10, on11, bw.w00, bw.w01, bw.w10, bw.w11);
                if (onv > 0.5f) {
                    freeflag = false;
                    xw = xt; yw = yt;
                    int oy = (int)yt, ox = (int)xt;
                    int iylo = (oy - 9) / 4; if (iylo < 0) iylo = 0;
                    int iyhi = (oy - 8) / 4; if (iyhi > GYC-1) iyhi = GYC-1;
                    int ixlo = (ox - 9) / 4; if (ixlo < 0) ixlo = 0;
                    int ixhi = (ox - 8) / 4; if (ixhi > GXC-1) ixhi = GXC-1;
                    for (int iy = iylo; iy <= iyhi; iy++) {
                        int w = (iy << 3) + (ixlo >> 5);
                        unsigned m1 = 1u << (ixlo & 31);
                        if (ixhi > ixlo) {
                            if ((ixlo & 31) == 31) {
                                atomicOr(&bm[w], m1);
                                atomicOr(&bm[w + 1], 1u);
                            } else {
                                atomicOr(&bm[w], m1 | (m1 << 1));
                            }
                        } else {
                            atomicOr(&bm[w], m1);
                        }
                    }
                }
            }
        }
        if (freeflag) mySt = -1.0f;
        myX = xw; myY = yw;
        X[(s+1)*NSLOT + t] = xw;
        Y[(s+1)*NSLOT + t] = yw;

        unsigned amask = __ballot_sync(0xffffffffu, freeflag);
        if (lane == 0) g_slotCnt[par][wid][b] = __popc(amask);

        gridbar();   // occupancy marks + slot counts + row s+1 visible

        // ===== Phase B': full-map snapshot + local scan + slot ranking + self-birth =====
        uint4 v = __ldcg((const uint4*)bm + tid);
        sh_bits[tid*4 + 0] = v.x; sh_bits[tid*4 + 1] = v.y;
        sh_bits[tid*4 + 2] = v.z; sh_bits[tid*4 + 3] = v.w;
        int zc = 128 - (__popc(v.x) + __popc(v.y) + __popc(v.z) + __popc(v.w));

        int inc = zc;
        #pragma unroll
        for (int d = 1; d < 32; d <<= 1) {
            int n = __shfl_up_sync(0xffffffffu, inc, d);
            if (lane >= d) inc += n;
        }
        if (lane == 31) sh_wsum[wid] = inc;

        int rcnt = 0, rpre = 0;
        #pragma unroll
        for (int k = 0; k < 8; k++) {
            int i = lane + 32*k;
            if (i < BB) {
                int c = __ldcg(&g_slotCnt[par][wid][i]);
                rcnt += c;
                if (i < b) rpre += c;
            }
        }
        int rowtot = __reduce_add_sync(0xffffffffu, rcnt);
        int rowpre = __reduce_add_sync(0xffffffffu, rpre);
        if (lane == 0) sh_rowtot[wid] = rowtot;
        __syncthreads();
        if (tid == 0) {
            int run = 0;
            #pragma unroll
            for (int i = 0; i < NWARP; i++) { int c = sh_wsum[i]; sh_woff[i] = run; run += c; }
            sh_nc = run;                               // total free candidates (identical in all blocks)
            int nfr = 0;
            #pragma unroll
            for (int i = 0; i < NWARP; i++) nfr += sh_rowtot[i];
            sh_nf = nfr;
        }
        __syncthreads();
        sh_pre[tid] = sh_woff[wid] + inc - zc;         // exclusive chunk prefix
        int base = rowpre;
        #pragma unroll
        for (int i = 0; i < NWARP; i++) if (i < wid) base += sh_rowtot[i];
        int myrank = freeflag ? base + __popc(amask & ((1u << lane) - 1u)) : -1;
        __syncthreads();

        // self-birth: k-th free slot takes the k-th zero bit (= k-th free candidate)
        int m = sh_nf < sh_nc ? sh_nf : sh_nc;
        if (myrank >= 0 && myrank < m) {
            int r = myrank;
            int lo = 0, hi = TT - 1;
            while (lo < hi) {                          // last chunk with prefix <= r
                int mid = (lo + hi + 1) >> 1;
                if (sh_pre[mid] <= r) lo = mid; else hi = mid - 1;
            }
            int k = r - sh_pre[lo];
            int wsel = -1, bit = 0;
            #pragma unroll
            for (int j = 0; j < 4; j++) {
                unsigned zw = ~sh_bits[lo*4 + j];
                int nz = __popc(zw);
                if (wsel < 0) {
                    if (k < nz) { wsel = lo*4 + j; bit = __fns(zw, 0, k + 1); }
                    else k -= nz;
                }
            }
            int iy = wsel >> 3;
            int ix = ((wsel & 7) << 5) | bit;
            myX = (float)(MARG + 4*ix);
            myY = (float)(MARG + 4*iy);
            mySt = (float)(s + 1);
            X[(s+1)*NSLOT + t] = myX;
            Y[(s+1)*NSLOT + t] = myY;
        }
        // no second barrier: everything phase C needed was block-local.
    }

    St[t] = mySt;
}

extern "C" void kernel_launch(void* const* d_in, const int* in_sizes, int n_in,
                              void* d_out, int out_size) {
    (void)in_sizes; (void)n_in; (void)out_size;
    const float* ff = (const float*)d_in[0];
    const float* fb = (const float*)d_in[1];
    float* out = (float*)d_out;
    dim3 g1(QTR/256, SS-1);
    k_onmask<<<g1, 256>>>(ff, fb);
    k_linker<<<BB, TT>>>(ff, out);
}

// round 14
// speedup vs baseline: 1.2313x; 1.0354x over previous
#include <cuda_runtime.h>

// Problem constants (fixed by setup_inputs: H=480, W=1024, S=32, margin=10, step=4)
#define HH     480
#define WW     1024
#define SS     32
#define HWIMG  (HH*WW)          // 491520
#define NSLOT  61440            // 2*H*W/step^2
#define GXC    252
#define GYC    116
#define GG     (GXC*GYC)        // 29232
#define MARG   10
#define BB     240              // persistent linker grid: 240 blocks x 256 = NSLOT threads
#define TT     256
#define NWARP  (TT/32)          // 8
#define WPI    (HWIMG/32)       // 15360 bitmask words per step
#define WPR    8                // occupancy words per grid row (256 bits >= GXC)
#define PWORDS 1024             // padded occupancy words (>= GYC*WPR = 928)
#define NSUB   8
#define SUBQ   (BB/NSUB)        // 30
#define QTR    (HWIMG/4)        // 122880

// Scratch (device globals; no allocations allowed)
// Occupancy bitmask, 3-buffer rotation (race-free): A(s) marks buf(s%3) and clears
// buf((s+1)%3); B'(s) reads buf(s%3). Every mark/read/clear pair is barrier-separated.
__device__ __align__(16) unsigned g_bits[3][PWORDS];
__device__ __align__(128) unsigned g_on[(SS-1)*WPI];  // precomputed fwd-bwd consistency bitmask
__device__ int g_slotCnt[2][NWARP][BB];               // parity-buffered (warp-row, block) free counts
struct __align__(128) PadCnt { unsigned v; unsigned pad[31]; };
__device__ PadCnt g_barSub[NSUB];
__device__ PadCnt g_barMaster;
__device__ __align__(128) volatile unsigned g_barGen;

// empty pattern: pad bits (ix>=252 in-row, rows>=GYC) are permanently "occupied"
__device__ __forceinline__ unsigned epat(int w) {
    return (w >= GYC*WPR) ? 0xFFFFFFFFu : (((w & 7) == 7) ? 0xF0000000u : 0u);
}

__device__ __forceinline__ void l2_prefetch(const void* p) {
    asm volatile("prefetch.global.L2 [%0];" :: "l"(p));
}

__device__ __forceinline__ void gridbar() {
    __syncthreads();
    if (threadIdx.x == 0) {
        __threadfence();                       // release: publish this block's writes
        unsigned gen = g_barGen;               // read BEFORE arrival (else lost-release race)
        bool last = false;
        if (atomicAdd(&g_barSub[blockIdx.x & (NSUB - 1)].v, 1u) == SUBQ - 1u) {
            if (atomicAdd(&g_barMaster.v, 1u) == NSUB - 1u) last = true;
        }
        if (last) {
            g_barMaster.v = 0;
            #pragma unroll
            for (int i = 0; i < NSUB; i++) g_barSub[i].v = 0;
            __threadfence();
            g_barGen = gen + 1u;
        } else {
            while (g_barGen == gen) { }
        }
    }
    __syncthreads();
}

// ---- math helpers: byte-identical to R1..R13 (rel_err was 0.0) ----
__device__ __forceinline__ float bil4(float s00, float s01, float s10, float s11,
                                      float w00, float w01, float w10, float w11) {
    return fmaf(s11, w11, fmaf(s10, w10, fmaf(s00, w00, __fmul_rn(s01, w01))));
}

struct BilW {
    int ix0, ix1, iy0, iy1;
    float w00, w01, w10, w11;
};

__device__ __forceinline__ BilW mkw(float x, float y) {
    BilW b;
    float x0f = floorf(x), y0f = floorf(y);
    float wx1 = __fsub_rn(x, x0f); float wx0 = __fsub_rn(1.0f, wx1);
    float wy1 = __fsub_rn(y, y0f); float wy0 = __fsub_rn(1.0f, wy1);
    int ix0 = (int)x0f; ix0 = ix0 < 0 ? 0 : (ix0 > WW-1 ? WW-1 : ix0);
    int iy0 = (int)y0f; iy0 = iy0 < 0 ? 0 : (iy0 > HH-1 ? HH-1 : iy0);
    b.ix0 = ix0; b.ix1 = (ix0+1 > WW-1) ? WW-1 : ix0+1;
    b.iy0 = iy0; b.iy1 = (iy0+1 > HH-1) ? HH-1 : iy0+1;
    b.w00 = __fmul_rn(wy0, wx0); b.w01 = __fmul_rn(wy0, wx1);
    b.w10 = __fmul_rn(wy1, wx0); b.w11 = __fmul_rn(wy1, wx1);
    return b;
}

__device__ __forceinline__ float on_at(const float* __restrict__ fb0,
                                       const float* __restrict__ fb1,
                                       float a0, float a1, int py, int px) {
    float xt = __fadd_rn((float)px, a0);
    float yt = __fadd_rn((float)py, a1);
    BilW b = mkw(xt, yt);
    float f00 = fb0[b.iy0*WW+b.ix0], f01 = fb0[b.iy0*WW+b.ix1];
    float f10 = fb0[b.iy1*WW+b.ix0], f11 = fb0[b.iy1*WW+b.ix1];
    float g00 = fb1[b.iy0*WW+b.ix0], g01 = fb1[b.iy0*WW+b.ix1];
    float g10 = fb1[b.iy1*WW+b.ix0], g11 = fb1[b.iy1*WW+b.ix1];
    float f0 = bil4(f00, f01, f10, f11, b.w00, b.w01, b.w10, b.w11);
    float f1 = bil4(g00, g01, g10, g11, b.w00, b.w01, b.w10, b.w11);
    float d0 = __fadd_rn(a0, f0), d1 = __fadd_rn(a1, f1);
    float diff = __fsqrt_rn(fmaf(d1, d1, __fmul_rn(d0, d0)));
    float m1 = __fsqrt_rn(fmaf(a1, a1, __fmul_rn(a0, a0)));
    float m2 = __fsqrt_rn(fmaf(f1, f1, __fmul_rn(f0, f0)));
    float mag = __fmul_rn(0.5f, __fadd_rn(m1, m2));
    return (diff <= fmaf(0.01f, mag, 0.1f)) ? 1.0f : 0.0f;
}

// ---------------- precompute: DRAM-roofline-bound (504MB unique traffic) ----------------
__global__ void __launch_bounds__(256) k_onmask(const float* __restrict__ ff,
                                                const float* __restrict__ fb) {
    int s = blockIdx.y;
    int p0 = blockIdx.x * 256 + threadIdx.x;
    int p1 = p0 + QTR;
    int p2 = p0 + 2*QTR;
    int p3 = p0 + 3*QTR;
    const float* ff0 = ff + (size_t)s * 2 * HWIMG;
    const float* ff1 = ff0 + HWIMG;
    const float* fb0 = fb + (size_t)s * 2 * HWIMG;
    const float* fb1 = fb0 + HWIMG;
    float a0 = ff0[p0], a1 = ff1[p0];
    float b0 = ff0[p1], b1 = ff1[p1];
    float c0 = ff0[p2], c1 = ff1[p2];
    float d0 = ff0[p3], d1 = ff1[p3];
    float o0 = on_at(fb0, fb1, a0, a1, p0 >> 10, p0 & 1023);
    float o1 = on_at(fb0, fb1, b0, b1, p1 >> 10, p1 & 1023);
    float o2 = on_at(fb0, fb1, c0, c1, p2 >> 10, p2 & 1023);
    float o3 = on_at(fb0, fb1, d0, d1, p3 >> 10, p3 & 1023);
    unsigned m0 = __ballot_sync(0xffffffffu, o0 != 0.0f);
    unsigned m1 = __ballot_sync(0xffffffffu, o1 != 0.0f);
    unsigned m2 = __ballot_sync(0xffffffffu, o2 != 0.0f);
    unsigned m3 = __ballot_sync(0xffffffffu, o3 != 0.0f);
    if ((threadIdx.x & 31) == 0) {
        g_on[s*WPI + (p0 >> 5)] = m0;
        g_on[s*WPI + (p1 >> 5)] = m1;
        g_on[s*WPI + (p2 >> 5)] = m2;
        g_on[s*WPI + (p3 >> 5)] = m3;
    }
}

// ---------------- persistent serial kernel, ONE grid barrier per step ----------------
// R13 linker + pipelined L2 prefetch of the NEXT step's ff slice and on-mask slice.
// Slot ownership warp-swizzled: thread (b, warp wi, lane) owns slot t = (b + BB*wi)*32 + lane.
__global__ void __launch_bounds__(TT, 2) k_linker(const float* __restrict__ ff,
                                                  float* __restrict__ out) {
    const int tid  = threadIdx.x;
    const int b    = blockIdx.x;
    const int lane = tid & 31;
    const int wid  = tid >> 5;
    const int t    = (b + BB*wid)*32 + lane;   // swizzled slot id
    const int u    = b * TT + tid;             // linear id (prefetch striping)

    float* X  = out;
    float* Y  = out + SS*NSLOT;
    float* St = out + 2*SS*NSLOT;

    __shared__ unsigned sh_bits[PWORDS];       // 4KB: full occupancy snapshot
    __shared__ int sh_pre[TT];                 // exclusive zero-count prefix per 4-word chunk
    __shared__ int sh_rowtot[NWARP], sh_wsum[NWARP], sh_woff[NWARP];
    __shared__ int sh_nf, sh_nc;

    // ---- init: per-thread persistent state + occupancy buffers; prefetch slice 0 ----
    float myX, myY, mySt;
    {
        bool ing = t < GG;
        myX  = ing ? (float)(MARG + 4*(t % GXC)) : 0.0f;
        myY  = ing ? (float)(MARG + 4*(t / GXC)) : 0.0f;
        mySt = ing ? 0.0f : -1.0f;
        X[t] = myX; Y[t] = myY;            // row 0
    }
    if (b < 12) {                           // 12 blocks x 256 = 3072 = 3*PWORDS
        int w = ((b & 3) << 8) + tid;
        g_bits[b >> 2][w] = epat(w);
    }
    // L2 prefetch of ff slice 0 (61440 threads x 64B == 2*HWIMG*4 bytes exactly)
    l2_prefetch((const char*)ff + (size_t)u * 64);
    if (u < 480) l2_prefetch((const char*)g_on + (size_t)u * 128);
    gridbar();   // occupancy init visible before A(0) marks

    for (int s = 0; s < SS - 1; s++) {
        const int par = s & 1;
        unsigned* bm = g_bits[s % 3];                  // marked here, read in B'(s)
        unsigned* bc = g_bits[(s + 1) % 3];            // cleared here (marked at A(s+1))
        const float* ff0 = ff + (size_t)s * 2 * HWIMG;
        const float* ff1 = ff0 + HWIMG;
        const unsigned* onw = g_on + s*WPI;

        // ===== Phase A: prefetch next slice, clear next buffer, advance, mark =====
        if (s < SS - 2) {
            // fire-and-forget L2 prefetch of step s+1's inputs (lands within ~6us)
            l2_prefetch((const char*)(ff + (size_t)(s + 1) * 2 * HWIMG) + (size_t)u * 64);
            if (u < 480) l2_prefetch((const char*)(g_on + (size_t)(s + 1) * WPI) + (size_t)u * 128);
        }
        if (b < 4) { int w = (b << 8) + tid; bc[w] = epat(w); }

        bool freeflag = true;                 // == (updated Start < 0)
        float xw = 0.0f, yw = 0.0f;
        if (mySt >= 0.0f) {
            BilW bw = mkw(myX, myY);
            float u00 = ff0[bw.iy0*WW+bw.ix0], u01 = ff0[bw.iy0*WW+bw.ix1];
            float u10 = ff0[bw.iy1*WW+bw.ix0], u11 = ff0[bw.iy1*WW+bw.ix1];
            float v00 = ff1[bw.iy0*WW+bw.ix0], v01 = ff1[bw.iy0*WW+bw.ix1];
            float v10 = ff1[bw.iy1*WW+bw.ix0], v11 = ff1[bw.iy1*WW+bw.ix1];
            float uvx = bil4(u00, u01, u10, u11, bw.w00, bw.w01, bw.w10, bw.w11);
            float uvy = bil4(v00, v01, v10, v11, bw.w00, bw.w01, bw.w10, bw.w11);
            float xt = __fadd_rn(myX, uvx);
            float yt = __fadd_rn(myY, uvy);
            bool marg = (xt > (float)MARG) && (yt > (float)MARG) &&
                        (xt < (float)(WW - MARG)) && (yt < (float)(HH - MARG));
            if (marg) {
                // bitmask probes reconstruct exactly 0.0f/1.0f (bit-identical to on_at)
                float on00 = (float)((onw[(bw.iy0<<5) + (bw.ix0>>5)] >> (bw.ix0&31)) & 1u);
                float on01 = (float)((onw[(bw.iy0<<5) + (bw.ix1>>5)] >> (bw.ix1&31)) & 1u);
                float on10 = (float)((onw[(bw.iy1<<5) + (bw.ix0>>5)] >> (bw.ix0&31)) & 1u);
                float on11 = (float)((onw[(bw.iy1<<5) + (bw.ix1>>5)] >> (bw.ix1&31)) & 1u);
                float onv = bil4(on00, on01, on10, on11, bw.w00, bw.w01, bw.w10, bw.w11);
                if (onv > 0.5f) {
                    freeflag = false;
                    xw = xt; yw = yt;
                    int oy = (int)yt, ox = (int)xt;
                    int iylo = (oy - 9) / 4; if (iylo < 0) iylo = 0;
                    int iyhi = (oy - 8) / 4; if (iyhi > GYC-1) iyhi = GYC-1;
                    int ixlo = (ox - 9) / 4; if (ixlo < 0) ixlo = 0;
                    int ixhi = (ox - 8) / 4; if (ixhi > GXC-1) ixhi = GXC-1;
                    for (int iy = iylo; iy <= iyhi; iy++) {
                        int w = (iy << 3) + (ixlo >> 5);
                        unsigned m1 = 1u << (ixlo & 31);
                        if (ixhi > ixlo) {
                            if ((ixlo & 31) == 31) {
                                atomicOr(&bm[w], m1);
                                atomicOr(&bm[w + 1], 1u);
                            } else {
                                atomicOr(&bm[w], m1 | (m1 << 1));
                            }
                        } else {
                            atomicOr(&bm[w], m1);
                        }
                    }
                }
            }
        }
        if (freeflag) mySt = -1.0f;
        myX = xw; myY = yw;
        X[(s+1)*NSLOT + t] = xw;
        Y[(s+1)*NSLOT + t] = yw;

        unsigned amask = __ballot_sync(0xffffffffu, freeflag);
        if (lane == 0) g_slotCnt[par][wid][b] = __popc(amask);

        gridbar();   // occupancy marks + slot counts + row s+1 visible

        // ===== Phase B': full-map snapshot + local scan + slot ranking + self-birth =====
        uint4 v = __ldcg((const uint4*)bm + tid);
        sh_bits[tid*4 + 0] = v.x; sh_bits[tid*4 + 1] = v.y;
        sh_bits[tid*4 + 2] = v.z; sh_bits[tid*4 + 3] = v.w;
        int zc = 128 - (__popc(v.x) + __popc(v.y) + __popc(v.z) + __popc(v.w));

        int inc = zc;
        #pragma unroll
        for (int d = 1; d < 32; d <<= 1) {
            int n = __shfl_up_sync(0xffffffffu, inc, d);
            if (lane >= d) inc += n;
        }
        if (lane == 31) sh_wsum[wid] = inc;

        int rcnt = 0, rpre = 0;
        #pragma unroll
        for (int k = 0; k < 8; k++) {
            int i = lane + 32*k;
            if (i < BB) {
                int c = __ldcg(&g_slotCnt[par][wid][i]);
                rcnt += c;
                if (i < b) rpre += c;
            }
        }
        int rowtot = __reduce_add_sync(0xffffffffu, rcnt);
        int rowpre = __reduce_add_sync(0xffffffffu, rpre);
        if (lane == 0) sh_rowtot[wid] = rowtot;
        __syncthreads();
        if (tid == 0) {
            int run = 0;
            #pragma unroll
            for (int i = 0; i < NWARP; i++) { int c = sh_wsum[i]; sh_woff[i] = run; run += c; }
            sh_nc = run;                               // total free candidates (identical in all blocks)
            int nfr = 0;
            #pragma unroll
            for (int i = 0; i < NWARP; i++) nfr += sh_rowtot[i];
            sh_nf = nfr;
        }
        __syncthreads();
        sh_pre[tid] = sh_woff[wid] + inc - zc;         // exclusive chunk prefix
        int base = rowpre;
        #pragma unroll
        for (int i = 0; i < NWARP; i++) if (i < wid) base += sh_rowtot[i];
        int myrank = freeflag ? base + __popc(amask & ((1u << lane) - 1u)) : -1;
        __syncthreads();

        // self-birth: k-th free slot takes the k-th zero bit (= k-th free candidate)
        int m = sh_nf < sh_nc ? sh_nf : sh_nc;
        if (myrank >= 0 && myrank < m) {
            int r = myrank;
            int lo = 0, hi = TT - 1;
            while (lo < hi) {                          // last chunk with prefix <= r
                int mid = (lo + hi + 1) >> 1;
                if (sh_pre[mid] <= r) lo = mid; else hi = mid - 1;
            }
            int k = r - sh_pre[lo];
            int wsel = -1, bit = 0;
            #pragma unroll
            for (int j = 0; j < 4; j++) {
                unsigned zw = ~sh_bits[lo*4 + j];
                int nz = __popc(zw);
                if (wsel < 0) {
                    if (k < nz) { wsel = lo*4 + j; bit = __fns(zw, 0, k + 1); }
                    else k -= nz;
                }
            }
            int iy = wsel >> 3;
            int ix = ((wsel & 7) << 5) | bit;
            myX = (float)(MARG + 4*ix);
            myY = (float)(MARG + 4*iy);
            mySt = (float)(s + 1);
            X[(s+1)*NSLOT + t] = myX;
            Y[(s+1)*NSLOT + t] = myY;
        }
        // no second barrier: everything phase C needed was block-local.
    }

    St[t] = mySt;
}

extern "C" void kernel_launch(void* const* d_in, const int* in_sizes, int n_in,
                              void* d_out, int out_size) {
    (void)in_sizes; (void)n_in; (void)out_size;
    const float* ff = (const float*)d_in[0];
    const float* fb = (const float*)d_in[1];
    float* out = (float*)d_out;
    dim3 g1(QTR/256, SS-1);
    k_onmask<<<g1, 256>>>(ff, fb);
    k_linker<<<BB, TT>>>(ff, out);
}

// round 15
// speedup vs baseline: 1.2450x; 1.0111x over previous
#include <cuda_runtime.h>

// Problem constants (fixed by setup_inputs: H=480, W=1024, S=32, margin=10, step=4)
#define HH     480
#define WW     1024
#define SS     32
#define HWIMG  (HH*WW)          // 491520
#define NSLOT  61440            // 2*H*W/step^2
#define GXC    252
#define GYC    116
#define GG     (GXC*GYC)        // 29232
#define MARG   10
#define BB     240              // persistent linker grid: 240 blocks x 256 = NSLOT threads
#define TT     256
#define NWARP  (TT/32)          // 8
#define WPI    (HWIMG/32)       // 15360 bitmask words per step
#define WPR    8                // occupancy words per grid row (256 bits >= GXC)
#define PWORDS 1024             // padded occupancy words (>= GYC*WPR = 928)
#define NSUB   8
#define SUBQ   (BB/NSUB)        // 30
#define QTR    (HWIMG/4)        // 122880

// Scratch (device globals; no allocations allowed)
// Occupancy bitmask, 3-buffer rotation (race-free): A(s) marks buf(s%3) and clears
// buf((s+1)%3); B'(s) reads buf(s%3). Every mark/read/clear pair is barrier-separated.
__device__ __align__(16) unsigned g_bits[3][PWORDS];
__device__ __align__(128) unsigned g_on[(SS-1)*WPI];  // precomputed fwd-bwd consistency bitmask
__device__ int g_slotCnt[2][NWARP][BB];               // parity-buffered (warp-row, block) free counts
// Monotonic counting barrier: counters NEVER reset (replay-safe); release = single gen bump.
struct __align__(128) PadCnt { unsigned v; unsigned pad[31]; };
__device__ PadCnt g_barSub[NSUB];
__device__ PadCnt g_barMaster;
__device__ __align__(128) volatile unsigned g_barGen;

// empty pattern: pad bits (ix>=252 in-row, rows>=GYC) are permanently "occupied"
__device__ __forceinline__ unsigned epat(int w) {
    return (w >= GYC*WPR) ? 0xFFFFFFFFu : (((w & 7) == 7) ? 0xF0000000u : 0u);
}

__device__ __forceinline__ void l2_prefetch(const void* p) {
    asm volatile("prefetch.global.L2 [%0];" :: "l"(p));
}

__device__ __forceinline__ void gridbar() {
    __syncthreads();
    if (threadIdx.x == 0) {
        __threadfence();                       // release: publish this block's writes
        unsigned gen = g_barGen;               // stable between barriers; read BEFORE arrival
        bool last = false;
        if (atomicAdd(&g_barSub[blockIdx.x & (NSUB - 1)].v, 1u) == (gen + 1u) * SUBQ - 1u) {
            if (atomicAdd(&g_barMaster.v, 1u) == (gen + 1u) * NSUB - 1u) last = true;
        }
        if (last) {
            __threadfence();
            g_barGen = gen + 1u;               // single-store release (no counter resets)
        } else {
            while (g_barGen == gen) { }
        }
    }
    __syncthreads();
}

// ---- math helpers: byte-identical to R1..R14 (rel_err was 0.0) ----
__device__ __forceinline__ float bil4(float s00, float s01, float s10, float s11,
                                      float w00, float w01, float w10, float w11) {
    return fmaf(s11, w11, fmaf(s10, w10, fmaf(s00, w00, __fmul_rn(s01, w01))));
}

struct BilW {
    int ix0, ix1, iy0, iy1;
    float w00, w01, w10, w11;
};

__device__ __forceinline__ BilW mkw(float x, float y) {
    BilW b;
    float x0f = floorf(x), y0f = floorf(y);
    float wx1 = __fsub_rn(x, x0f); float wx0 = __fsub_rn(1.0f, wx1);
    float wy1 = __fsub_rn(y, y0f); float wy0 = __fsub_rn(1.0f, wy1);
    int ix0 = (int)x0f; ix0 = ix0 < 0 ? 0 : (ix0 > WW-1 ? WW-1 : ix0);
    int iy0 = (int)y0f; iy0 = iy0 < 0 ? 0 : (iy0 > HH-1 ? HH-1 : iy0);
    b.ix0 = ix0; b.ix1 = (ix0+1 > WW-1) ? WW-1 : ix0+1;
    b.iy0 = iy0; b.iy1 = (iy0+1 > HH-1) ? HH-1 : iy0+1;
    b.w00 = __fmul_rn(wy0, wx0); b.w01 = __fmul_rn(wy0, wx1);
    b.w10 = __fmul_rn(wy1, wx0); b.w11 = __fmul_rn(wy1, wx1);
    return b;
}

__device__ __forceinline__ float on_at(const float* __restrict__ fb0,
                                       const float* __restrict__ fb1,
                                       float a0, float a1, int py, int px) {
    float xt = __fadd_rn((float)px, a0);
    float yt = __fadd_rn((float)py, a1);
    BilW b = mkw(xt, yt);
    float f00 = fb0[b.iy0*WW+b.ix0], f01 = fb0[b.iy0*WW+b.ix1];
    float f10 = fb0[b.iy1*WW+b.ix0], f11 = fb0[b.iy1*WW+b.ix1];
    float g00 = fb1[b.iy0*WW+b.ix0], g01 = fb1[b.iy0*WW+b.ix1];
    float g10 = fb1[b.iy1*WW+b.ix0], g11 = fb1[b.iy1*WW+b.ix1];
    float f0 = bil4(f00, f01, f10, f11, b.w00, b.w01, b.w10, b.w11);
    float f1 = bil4(g00, g01, g10, g11, b.w00, b.w01, b.w10, b.w11);
    float d0 = __fadd_rn(a0, f0), d1 = __fadd_rn(a1, f1);
    float diff = __fsqrt_rn(fmaf(d1, d1, __fmul_rn(d0, d0)));
    float m1 = __fsqrt_rn(fmaf(a1, a1, __fmul_rn(a0, a0)));
    float m2 = __fsqrt_rn(fmaf(f1, f1, __fmul_rn(f0, f0)));
    float mag = __fmul_rn(0.5f, __fadd_rn(m1, m2));
    return (diff <= fmaf(0.01f, mag, 0.1f)) ? 1.0f : 0.0f;
}

// ---------------- precompute: DRAM-roofline-bound (504MB unique traffic) ----------------
__global__ void __launch_bounds__(256) k_onmask(const float* __restrict__ ff,
                                                const float* __restrict__ fb) {
    int s = blockIdx.y;
    int p0 = blockIdx.x * 256 + threadIdx.x;
    int p1 = p0 + QTR;
    int p2 = p0 + 2*QTR;
    int p3 = p0 + 3*QTR;
    const float* ff0 = ff + (size_t)s * 2 * HWIMG;
    const float* ff1 = ff0 + HWIMG;
    const float* fb0 = fb + (size_t)s * 2 * HWIMG;
    const float* fb1 = fb0 + HWIMG;
    float a0 = ff0[p0], a1 = ff1[p0];
    float b0 = ff0[p1], b1 = ff1[p1];
    float c0 = ff0[p2], c1 = ff1[p2];
    float d0 = ff0[p3], d1 = ff1[p3];
    float o0 = on_at(fb0, fb1, a0, a1, p0 >> 10, p0 & 1023);
    float o1 = on_at(fb0, fb1, b0, b1, p1 >> 10, p1 & 1023);
    float o2 = on_at(fb0, fb1, c0, c1, p2 >> 10, p2 & 1023);
    float o3 = on_at(fb0, fb1, d0, d1, p3 >> 10, p3 & 1023);
    unsigned m0 = __ballot_sync(0xffffffffu, o0 != 0.0f);
    unsigned m1 = __ballot_sync(0xffffffffu, o1 != 0.0f);
    unsigned m2 = __ballot_sync(0xffffffffu, o2 != 0.0f);
    unsigned m3 = __ballot_sync(0xffffffffu, o3 != 0.0f);
    if ((threadIdx.x & 31) == 0) {
        g_on[s*WPI + (p0 >> 5)] = m0;
        g_on[s*WPI + (p1 >> 5)] = m1;
        g_on[s*WPI + (p2 >> 5)] = m2;
        g_on[s*WPI + (p3 >> 5)] = m3;
    }
}

// ---------------- persistent serial kernel, ONE grid barrier per step ----------------
// R14 + (a) on-probe loads hoisted out of the marg branch (issue in parallel with the
// 8 ff gathers — one fewer L2 round-trip on the critical path), (b) monotonic barrier.
__global__ void __launch_bounds__(TT, 2) k_linker(const float* __restrict__ ff,
                                                  float* __restrict__ out) {
    const int tid  = threadIdx.x;
    const int b    = blockIdx.x;
    const int lane = tid & 31;
    const int wid  = tid >> 5;
    const int t    = (b + BB*wid)*32 + lane;   // swizzled slot id
    const int u    = b * TT + tid;             // linear id (prefetch striping)

    float* X  = out;
    float* Y  = out + SS*NSLOT;
    float* St = out + 2*SS*NSLOT;

    __shared__ unsigned sh_bits[PWORDS];       // 4KB: full occupancy snapshot
    __shared__ int sh_pre[TT];                 // exclusive zero-count prefix per 4-word chunk
    __shared__ int sh_rowtot[NWARP], sh_wsum[NWARP], sh_woff[NWARP];
    __shared__ int sh_nf, sh_nc;

    // ---- init: per-thread persistent state + occupancy buffers; prefetch slice 0 ----
    float myX, myY, mySt;
    {
        bool ing = t < GG;
        myX  = ing ? (float)(MARG + 4*(t % GXC)) : 0.0f;
        myY  = ing ? (float)(MARG + 4*(t / GXC)) : 0.0f;
        mySt = ing ? 0.0f : -1.0f;
        X[t] = myX; Y[t] = myY;            // row 0
    }
    if (b < 12) {                           // 12 blocks x 256 = 3072 = 3*PWORDS
        int w = ((b & 3) << 8) + tid;
        g_bits[b >> 2][w] = epat(w);
    }
    // L2 prefetch of ff slice 0 (61440 threads x 64B == 2*HWIMG*4 bytes exactly)
    l2_prefetch((const char*)ff + (size_t)u * 64);
    if (u < 480) l2_prefetch((const char*)g_on + (size_t)u * 128);
    gridbar();   // occupancy init visible before A(0) marks

    for (int s = 0; s < SS - 1; s++) {
        const int par = s & 1;
        unsigned* bm = g_bits[s % 3];                  // marked here, read in B'(s)
        unsigned* bc = g_bits[(s + 1) % 3];            // cleared here (marked at A(s+1))
        const float* ff0 = ff + (size_t)s * 2 * HWIMG;
        const float* ff1 = ff0 + HWIMG;
        const unsigned* onw = g_on + s*WPI;

        // ===== Phase A: prefetch next slice, clear next buffer, advance, mark =====
        if (s < SS - 2) {
            // fire-and-forget L2 prefetch of step s+1's inputs (lands within ~5us)
            l2_prefetch((const char*)(ff + (size_t)(s + 1) * 2 * HWIMG) + (size_t)u * 64);
            if (u < 480) l2_prefetch((const char*)(g_on + (size_t)(s + 1) * WPI) + (size_t)u * 128);
        }
        if (b < 4) { int w = (b << 8) + tid; bc[w] = epat(w); }

        bool freeflag = true;                 // == (updated Start < 0)
        float xw = 0.0f, yw = 0.0f;
        if (mySt >= 0.0f) {
            BilW bw = mkw(myX, myY);
            // issue ALL 12 loads together: 4 on-probe words (indices depend only on bw,
            // not on the gathers) + 8 ff gathers — one L2 round-trip, not two
            unsigned pw00 = onw[(bw.iy0<<5) + (bw.ix0>>5)];
            unsigned pw01 = onw[(bw.iy0<<5) + (bw.ix1>>5)];
            unsigned pw10 = onw[(bw.iy1<<5) + (bw.ix0>>5)];
            unsigned pw11 = onw[(bw.iy1<<5) + (bw.ix1>>5)];
            float u00 = ff0[bw.iy0*WW+bw.ix0], u01 = ff0[bw.iy0*WW+bw.ix1];
            float u10 = ff0[bw.iy1*WW+bw.ix0], u11 = ff0[bw.iy1*WW+bw.ix1];
            float v00 = ff1[bw.iy0*WW+bw.ix0], v01 = ff1[bw.iy0*WW+bw.ix1];
            float v10 = ff1[bw.iy1*WW+bw.ix0], v11 = ff1[bw.iy1*WW+bw.ix1];
            float uvx = bil4(u00, u01, u10, u11, bw.w00, bw.w01, bw.w10, bw.w11);
            float uvy = bil4(v00, v01, v10, v11, bw.w00, bw.w01, bw.w10, bw.w11);
            float xt = __fadd_rn(myX, uvx);
            float yt = __fadd_rn(myY, uvy);
            bool marg = (xt > (float)MARG) && (yt > (float)MARG) &&
                        (xt < (float)(WW - MARG)) && (yt < (float)(HH - MARG));
            if (marg) {
                // bitmask probes reconstruct exactly 0.0f/1.0f (bit-identical to on_at)
                float on00 = (float)((pw00 >> (bw.ix0&31)) & 1u);
                float on01 = (float)((pw01 >> (bw.ix1&31)) & 1u);
                float on10 = (float)((pw10 >> (bw.ix0&31)) & 1u);
                float on11 = (float)((pw11 >> (bw.ix1&31)) & 1u);
                float onv = bil4(on00, on01, on10, on11, bw.w00, bw.w01, bw.w10, bw.w11);
                if (onv > 0.5f) {
                    freeflag = false;
                    xw = xt; yw = yt;
                    int oy = (int)yt, ox = (int)xt;
                    int iylo = (oy - 9) / 4; if (iylo < 0) iylo = 0;
                    int iyhi = (oy - 8) / 4; if (iyhi > GYC-1) iyhi = GYC-1;
                    int ixlo = (ox - 9) / 4; if (ixlo < 0) ixlo = 0;
                    int ixhi = (ox - 8) / 4; if (ixhi > GXC-1) ixhi = GXC-1;
                    for (int iy = iylo; iy <= iyhi; iy++) {
                        int w = (iy << 3) + (ixlo >> 5);
                        unsigned m1 = 1u << (ixlo & 31);
                        if (ixhi > ixlo) {
                            if ((ixlo & 31) == 31) {
                                atomicOr(&bm[w], m1);
                                atomicOr(&bm[w + 1], 1u);
                            } else {
                                atomicOr(&bm[w], m1 | (m1 << 1));
                            }
                        } else {
                            atomicOr(&bm[w], m1);
                        }
                    }
                }
            }
        }
        if (freeflag) mySt = -1.0f;
        myX = xw; myY = yw;
        X[(s+1)*NSLOT + t] = xw;
        Y[(s+1)*NSLOT + t] = yw;

        unsigned amask = __ballot_sync(0xffffffffu, freeflag);
        if (lane == 0) g_slotCnt[par][wid][b] = __popc(amask);

        gridbar();   // occupancy marks + slot counts + row s+1 visible

        // ===== Phase B': full-map snapshot + local scan + slot ranking + self-birth =====
        uint4 v = __ldcg((const uint4*)bm + tid);
        sh_bits[tid*4 + 0] = v.x; sh_bits[tid*4 + 1] = v.y;
        sh_bits[tid*4 + 2] = v.z; sh_bits[tid*4 + 3] = v.w;
        int zc = 128 - (__popc(v.x) + __popc(v.y) + __popc(v.z) + __popc(v.w));

        int inc = zc;
        #pragma unroll
        for (int d = 1; d < 32; d <<= 1) {
            int n = __shfl_up_sync(0xffffffffu, inc, d);
            if (lane >= d) inc += n;
        }
        if (lane == 31) sh_wsum[wid] = inc;

        int rcnt = 0, rpre = 0;
        #pragma unroll
        for (int k = 0; k < 8; k++) {
            int i = lane + 32*k;
            if (i < BB) {
                int c = __ldcg(&g_slotCnt[par][wid][i]);
                rcnt += c;
                if (i < b) rpre += c;
            }
        }
        int rowtot = __reduce_add_sync(0xffffffffu, rcnt);
        int rowpre = __reduce_add_sync(0xffffffffu, rpre);
        if (lane == 0) sh_rowtot[wid] = rowtot;
        __syncthreads();
        if (tid == 0) {
            int run = 0;
            #pragma unroll
            for (int i = 0; i < NWARP; i++) { int c = sh_wsum[i]; sh_woff[i] = run; run += c; }
            sh_nc = run;                               // total free candidates (identical in all blocks)
            int nfr = 0;
            #pragma unroll
            for (int i = 0; i < NWARP; i++) nfr += sh_rowtot[i];
            sh_nf = nfr;
        }
        __syncthreads();
        sh_pre[tid] = sh_woff[wid] + inc - zc;         // exclusive chunk prefix
        int base = rowpre;
        #pragma unroll
        for (int i = 0; i < NWARP; i++) if (i < wid) base += sh_rowtot[i];
        int myrank = freeflag ? base + __popc(amask & ((1u << lane) - 1u)) : -1;
        __syncthreads();

        // self-birth: k-th free slot takes the k-th zero bit (= k-th free candidate)
        int m = sh_nf < sh_nc ? sh_nf : sh_nc;
        if (myrank >= 0 && myrank < m) {
            int r = myrank;
            int lo = 0, hi = TT - 1;
            while (lo < hi) {                          // last chunk with prefix <= r
                int mid = (lo + hi + 1) >> 1;
                if (sh_pre[mid] <= r) lo = mid; else hi = mid - 1;
            }
            int k = r - sh_pre[lo];
            int wsel = -1, bit = 0;
            #pragma unroll
            for (int j = 0; j < 4; j++) {
                unsigned zw = ~sh_bits[lo*4 + j];
                int nz = __popc(zw);
                if (wsel < 0) {
                    if (k < nz) { wsel = lo*4 + j; bit = __fns(zw, 0, k + 1); }
                    else k -= nz;
                }
            }
            int iy = wsel >> 3;
            int ix = ((wsel & 7) << 5) | bit;
            myX = (float)(MARG + 4*ix);
            myY = (float)(MARG + 4*iy);
            mySt = (float)(s + 1);
            X[(s+1)*NSLOT + t] = myX;
            Y[(s+1)*NSLOT + t] = myY;
        }
        // no second barrier: everything phase C needed was block-local.
    }

    St[t] = mySt;
}

extern "C" void kernel_launch(void* const* d_in, const int* in_sizes, int n_in,
                              void* d_out, int out_size) {
    (void)in_sizes; (void)n_in; (void)out_size;
    const float* ff = (const float*)d_in[0];
    const float* fb = (const float*)d_in[1];
    float* out = (float*)d_out;
    dim3 g1(QTR/256, SS-1);
    k_onmask<<<g1, 256>>>(ff, fb);
    k_linker<<<BB, TT>>>(ff, out);
}